// round 13
// baseline (speedup 1.0000x reference)
#include <cuda_runtime.h>
#include <cuda_fp16.h>
#include <cstdint>
#include <math.h>

#define DIM 2048
#define NH 16
#define HD 128
#define BSZ 2
#define SEQLEN 2048
#define MROWS (BSZ * SEQLEN)

// Scratch (static device arrays — allocation-free per harness rules)
__device__ __half g_q[(size_t)MROWS * DIM];
__device__ __half g_k[(size_t)MROWS * DIM];
__device__ __half g_v[(size_t)MROWS * DIM];
__device__ __half g_att[(size_t)MROWS * DIM];
__device__ __half g_xh[(size_t)MROWS * DIM];
__device__ __half g_wqh[(size_t)DIM * DIM];
__device__ __half g_wkh[(size_t)DIM * DIM];
__device__ __half g_wvh[(size_t)DIM * DIM];
__device__ __half g_woh[(size_t)DIM * DIM];

__device__ __forceinline__ void mma_f16(float* c, const uint32_t* a,
                                        const uint32_t* b) {
    asm volatile(
        "mma.sync.aligned.m16n8k16.row.col.f32.f16.f16.f32 "
        "{%0,%1,%2,%3}, {%4,%5,%6,%7}, {%8,%9}, {%0,%1,%2,%3};"
        : "+f"(c[0]), "+f"(c[1]), "+f"(c[2]), "+f"(c[3])
        : "r"(a[0]), "r"(a[1]), "r"(a[2]), "r"(a[3]), "r"(b[0]), "r"(b[1]));
}

__device__ __forceinline__ void ldmatrix_x2_trans(uint32_t& r0, uint32_t& r1,
                                                  uint32_t addr) {
    asm volatile("ldmatrix.sync.aligned.m8n8.x2.trans.shared.b16 {%0,%1}, [%2];"
                 : "=r"(r0), "=r"(r1) : "r"(addr));
}

__device__ __forceinline__ uint32_t smem_u32(const void* p) {
    uint32_t a;
    asm("{ .reg .u64 t; cvta.to.shared.u64 t, %1; cvt.u32.u64 %0, t; }"
        : "=r"(a) : "l"(p));
    return a;
}
__device__ __forceinline__ void cp_async16(uint32_t dst, const void* src) {
    asm volatile("cp.async.cg.shared.global [%0], [%1], 16;"
                 :: "r"(dst), "l"(src) : "memory");
}
#define CP_COMMIT() asm volatile("cp.async.commit_group;" ::: "memory")
#define CP_WAIT(N)  asm volatile("cp.async.wait_group %0;" :: "n"(N) : "memory")

// ---------------------------------------------------------------------------
// fp32 -> fp16 elementwise convert (vectorized)
// ---------------------------------------------------------------------------
__global__ __launch_bounds__(256) void cvt_f16_kernel(
    const float4* __restrict__ in, uint2* __restrict__ out, int n4)
{
    int i = blockIdx.x * blockDim.x + threadIdx.x;
    if (i >= n4) return;
    float4 v = in[i];
    __half2 h0 = __floats2half2_rn(v.x, v.y);
    __half2 h1 = __floats2half2_rn(v.z, v.w);
    uint2 u;
    u.x = *(uint32_t*)&h0;
    u.y = *(uint32_t*)&h1;
    out[i] = u;
}

// ===========================================================================
// fp16 mma.sync GEMM: C = A * B^T. A [M][K], B [N][K] fp16.
// 128x128x64 block tile, 8 warps (2x4), warp tile 64x32, m16n8k16,
// 3-buffer cp.async pipeline, 2 CTAs/SM. 32 mainloop stages (half the syncs).
// qkv_mode: outputs fp16 with RoPE (z<2) and q-scale (z==0); else fp32 out.
// ===========================================================================
#define GBM 128
#define GBN 128
#define GBK 64
#define GSTH 72                 // halfs per smem row (36 words: conflict-free)
#define GSTW 36
#define GT_H (GBM * GSTH)       // 9216 halfs
#define GT_W (GT_H / 2)         // 4608 words
#define GSTAGE_H (2 * GT_H)
#define GNBUF 3
#define GEMM_SMEM (GNBUF * GSTAGE_H * 2)   // 110592 bytes
#define NSTAGE (DIM / GBK)                 // 32

__global__ __launch_bounds__(256, 2) void gemm_f16_kernel(
    const __half* __restrict__ A,
    const __half* __restrict__ B0, const __half* __restrict__ B1,
    const __half* __restrict__ B2,
    void* C0, void* C1, void* C2,
    const float* __restrict__ cosf, const float* __restrict__ sinf,
    int qkv_mode)
{
    extern __shared__ __half smh[];
    const int tid = threadIdx.x;
    const int wid = tid >> 5;
    const int lane = tid & 31;
    const int warp_m = wid >> 2;
    const int warp_n = wid & 3;
    const int bm = blockIdx.y * GBM;
    const int bn = blockIdx.x * GBN;
    const int z = blockIdx.z;

    const __half* B = (z == 0) ? B0 : (z == 1) ? B1 : B2;
    void* C = (z == 0) ? C0 : (z == 1) ? C1 : C2;

    const uint32_t smem_base = smem_u32(smh);

    float acc[4][4][4];
#pragma unroll
    for (int i = 0; i < 4; ++i)
#pragma unroll
        for (int j = 0; j < 4; ++j)
#pragma unroll
            for (int r = 0; r < 4; ++r) acc[i][j][r] = 0.0f;

    // per-stage: A,B tiles 128 rows x 64 halfs; 8 x 16B chunks per row;
    // each thread: 4 chunks A + 4 chunks B (row pr, chunks pc*4 .. pc*4+3)
    const int pr = tid >> 1;       // 0..127
    const int pc = tid & 1;        // 0..1
    auto prefetch = [&](int s) {
        const int k0 = s * GBK;
        const uint32_t sb = smem_base + (s % GNBUF) * (GSTAGE_H * 2);
#pragma unroll
        for (int i = 0; i < 4; ++i) {
            int c = pc * 4 + i;    // 0..7
            cp_async16(sb + (pr * GSTH + c * 8) * 2,
                       A + (size_t)(bm + pr) * DIM + k0 + c * 8);
            cp_async16(sb + (GT_H + pr * GSTH + c * 8) * 2,
                       B + (size_t)(bn + pr) * DIM + k0 + c * 8);
        }
        CP_COMMIT();
    };

    prefetch(0);
    prefetch(1);

    const int arow = warp_m * 64 + (lane >> 2);
    const int brow = warp_n * 32 + (lane >> 2);
    const int kc = lane & 3;

    for (int s = 0; s < NSTAGE; ++s) {
        if (s + 1 < NSTAGE) { CP_WAIT(1); } else { CP_WAIT(0); }
        __syncthreads();
        if (s + 2 < NSTAGE) prefetch(s + 2);   // after sync: WAR-safe

        const uint32_t* Asm = (const uint32_t*)smh + (s % GNBUF) * (GSTAGE_H / 2);
        const uint32_t* Bsm = Asm + GT_W;

#pragma unroll
        for (int ks = 0; ks < 4; ++ks) {
            uint32_t af[4][4];
#pragma unroll
            for (int mt = 0; mt < 4; ++mt) {
                const uint32_t* p = Asm + (arow + mt * 16) * GSTW + ks * 8 + kc;
                af[mt][0] = p[0];
                af[mt][1] = p[8 * GSTW];
                af[mt][2] = p[4];
                af[mt][3] = p[8 * GSTW + 4];
            }
            uint32_t bf[4][2];
#pragma unroll
            for (int nt = 0; nt < 4; ++nt) {
                const uint32_t* p = Bsm + (brow + nt * 8) * GSTW + ks * 8 + kc;
                bf[nt][0] = p[0];
                bf[nt][1] = p[4];
            }
#pragma unroll
            for (int mt = 0; mt < 4; ++mt)
#pragma unroll
                for (int nt = 0; nt < 4; ++nt)
                    mma_f16(acc[mt][nt], af[mt], bf[nt]);
        }
    }

    // epilogue
    const float qs = (qkv_mode && z == 0) ? 0.08838834764831845f : 1.0f;
#pragma unroll
    for (int mt = 0; mt < 4; ++mt) {
        const int row0 = bm + warp_m * 64 + mt * 16 + (lane >> 2);
        const int s0 = row0 & (SEQLEN - 1);
#pragma unroll
        for (int nt = 0; nt < 4; ++nt) {
            const int col = bn + warp_n * 32 + nt * 8 + (lane & 3) * 2;
            float v0 = acc[mt][nt][0], v1 = acc[mt][nt][1];
            float v2 = acc[mt][nt][2], v3 = acc[mt][nt][3];
            if (qkv_mode) {
                if (z < 2) {   // RoPE for q, k
                    const int p = (col & (HD - 1)) >> 1;
                    float c0 = cosf[s0 * 64 + p], n0 = sinf[s0 * 64 + p];
                    float c1 = cosf[(s0 + 8) * 64 + p], n1 = sinf[(s0 + 8) * 64 + p];
                    float t0 = v0 * c0 - v1 * n0;
                    v1 = v0 * n0 + v1 * c0; v0 = t0;
                    float t2 = v2 * c1 - v3 * n1;
                    v3 = v2 * n1 + v3 * c1; v2 = t2;
                }
                __half* Ch = (__half*)C;
                *(__half2*)(Ch + (size_t)row0 * DIM + col) =
                    __floats2half2_rn(v0 * qs, v1 * qs);
                *(__half2*)(Ch + (size_t)(row0 + 8) * DIM + col) =
                    __floats2half2_rn(v2 * qs, v3 * qs);
            } else {
                float* Cf = (float*)C;
                *(float2*)(Cf + (size_t)row0 * DIM + col) = make_float2(v0, v1);
                *(float2*)(Cf + (size_t)(row0 + 8) * DIM + col) = make_float2(v2, v3);
            }
        }
    }
}

// ===========================================================================
// Flash attention, fp16 mma.sync. BQ=64, BKV=64, 256 threads, 2 CTAs/SM.
// Q pre-scaled by 1/sqrt(hd). QK^T warp tile 16x32; PV 16x64 (V via
// ldmatrix.trans). P (fp16) is aliased into the DEAD K[buf] stage buffer:
// K[buf] reads end before the post-scores sync; next prefetch into K[buf]
// happens after the loop-end sync, so the overlay is race-free.
// ===========================================================================
#define BQ 64
#define BKV 64
#define FSTH 136          // Q/K/V smem stride in halfs (68 words)
#define FSTW 68
#define FS_ST 68          // S stride (floats)
#define FP_STH 72         // P stride (halfs) = 36 words: conflict-free A-frags
#define FP_STW 36

#define Q_BYTES (BQ * FSTH * 2)           // 17408
#define KV_TILE_BYTES (BKV * FSTH * 2)    // 17408
#define OFFB_Q 0
#define OFFB_K (OFFB_Q + Q_BYTES)                 // 17408
#define OFFB_V (OFFB_K + 2 * KV_TILE_BYTES)       // 52224
#define OFFB_S (OFFB_V + 2 * KV_TILE_BYTES)       // 87040
#define OFFB_RED (OFFB_S + BQ * FS_ST * 4)        // 104448
#define OFFB_M (OFFB_RED + 256 * 4)               // 105472
#define OFFB_L (OFFB_M + BQ * 4)
#define OFFB_SC (OFFB_L + BQ * 4)
#define FLASH_SMEM_BYTES (OFFB_SC + BQ * 4)       // 106240

__global__ __launch_bounds__(256, 2) void flash_kernel(
    const __half* __restrict__ Q, const __half* __restrict__ K,
    const __half* __restrict__ V, __half* __restrict__ O)
{
    extern __shared__ char smc[];
    __half* Qs = (__half*)(smc + OFFB_Q);
    float* Ss = (float*)(smc + OFFB_S);
    float* red = (float*)(smc + OFFB_RED);
    float* m_s = (float*)(smc + OFFB_M);
    float* l_s = (float*)(smc + OFFB_L);
    float* sc_s = (float*)(smc + OFFB_SC);

    const int qt = (int)gridDim.x - 1 - (int)blockIdx.x;   // heavy tiles first
    const int bh = blockIdx.y;
    const int b = bh >> 4;
    const int h = bh & 15;
    const int tid = threadIdx.x;
    const int wid = tid >> 5;
    const int lane = tid & 31;
    const int warp_m = wid >> 1;     // 0..3
    const int warp_n = wid & 1;      // 0..1
    const int lr = lane >> 2;        // 0..7
    const int kc = lane & 3;         // 0..3

    const size_t head_base = (size_t)b * SEQLEN * DIM + (size_t)h * HD;
    const uint32_t q_su = smem_u32(smc + OFFB_Q);
    const uint32_t k_su = smem_u32(smc + OFFB_K);
    const uint32_t v_su = smem_u32(smc + OFFB_V);

    // Load Q tile via cp.async (fp16, already scaled)
    {
        const __half* Qg = Q + head_base + (size_t)(qt * BQ) * DIM;
#pragma unroll
        for (int i = 0; i < 4; ++i) {
            int e = tid + i * 256;        // 0..1023
            int r = e >> 4;               // 0..63
            int c = e & 15;               // 16B chunk (8 halfs)
            cp_async16(q_su + (r * FSTH + c * 8) * 2,
                       Qg + (size_t)r * DIM + c * 8);
        }
        CP_COMMIT();
    }
    if (tid < BQ) { m_s[tid] = -1e30f; l_s[tid] = 0.0f; }

    float accO[8][4];
#pragma unroll
    for (int i = 0; i < 8; ++i)
#pragma unroll
        for (int r = 0; r < 4; ++r) accO[i][r] = 0.0f;

    auto prefetch = [&](int kt, int buf) {
        const __half* Kg = K + head_base + (size_t)(kt * BKV) * DIM;
        const __half* Vg = V + head_base + (size_t)(kt * BKV) * DIM;
        const uint32_t kb = k_su + buf * KV_TILE_BYTES;
        const uint32_t vb = v_su + buf * KV_TILE_BYTES;
#pragma unroll
        for (int i = 0; i < 4; ++i) {
            int e = tid + i * 256;        // 0..1023
            int r = e >> 4;               // 0..63
            int c = e & 15;
            cp_async16(kb + (r * FSTH + c * 8) * 2, Kg + (size_t)r * DIM + c * 8);
            cp_async16(vb + (r * FSTH + c * 8) * 2, Vg + (size_t)r * DIM + c * 8);
        }
        CP_COMMIT();
    };

    prefetch(0, 0);
    __syncthreads();

    const int ntiles = qt + 1;
    for (int kt = 0; kt < ntiles; ++kt) {
        const int buf = kt & 1;
        const bool more = (kt + 1 < ntiles);
        if (more) prefetch(kt + 1, buf ^ 1);
        if (more) { CP_WAIT(1); } else { CP_WAIT(0); }
        __syncthreads();

        // ---- QK^T: 16x32 warp tile, m16n8k16, ks = HD/16 = 8 ----
        float accS[4][4];
#pragma unroll
        for (int nt = 0; nt < 4; ++nt)
#pragma unroll
            for (int r = 0; r < 4; ++r) accS[nt][r] = 0.0f;

        const uint32_t* Qw = (const uint32_t*)Qs + (warp_m * 16 + lr) * FSTW + kc;
        const uint32_t* Kw = (const uint32_t*)(smc + OFFB_K) +
                             buf * (KV_TILE_BYTES / 4) +
                             (warp_n * 32 + lr) * FSTW + kc;
#pragma unroll
        for (int ks = 0; ks < 8; ++ks) {
            uint32_t a[4];
            const uint32_t* ap = Qw + ks * 8;
            a[0] = ap[0];
            a[1] = ap[8 * FSTW];
            a[2] = ap[4];
            a[3] = ap[8 * FSTW + 4];
#pragma unroll
            for (int nt = 0; nt < 4; ++nt) {
                const uint32_t* bp = Kw + nt * 8 * FSTW + ks * 8;
                uint32_t bfr[2];
                bfr[0] = bp[0];
                bfr[1] = bp[4];
                mma_f16(accS[nt], a, bfr);
            }
        }

        // ---- store scores fp32 (causal mask on diagonal tile kt==qt) ----
        const bool diag = (kt == qt);
        const int r0 = warp_m * 16 + lr;
#pragma unroll
        for (int nt = 0; nt < 4; ++nt) {
            int cb = warp_n * 32 + nt * 8 + kc * 2;
            float v0 = accS[nt][0], v1 = accS[nt][1];
            float v2 = accS[nt][2], v3 = accS[nt][3];
            if (diag) {
                if (cb > r0)          v0 = -1e30f;
                if (cb + 1 > r0)      v1 = -1e30f;
                if (cb > r0 + 8)      v2 = -1e30f;
                if (cb + 1 > r0 + 8)  v3 = -1e30f;
            }
            Ss[r0 * FS_ST + cb]           = v0;
            Ss[r0 * FS_ST + cb + 1]       = v1;
            Ss[(r0 + 8) * FS_ST + cb]     = v2;
            Ss[(r0 + 8) * FS_ST + cb + 1] = v3;
        }
        __syncthreads();   // also: all K[buf] reads complete (P overlay safe)

        // ---- softmax: 4 threads per row, 16 cols each ----
        const int srow = tid & 63;
        const int sq = tid >> 6;
        {
            float mx = -1e30f;
#pragma unroll
            for (int j = 0; j < 16; ++j)
                mx = fmaxf(mx, Ss[srow * FS_ST + sq * 16 + j]);
            red[sq * 64 + srow] = mx;
        }
        __syncthreads();
        if (tid < BQ) {
            float mold = m_s[tid];
            float mt = fmaxf(fmaxf(red[tid], red[64 + tid]),
                             fmaxf(red[128 + tid], red[192 + tid]));
            float mnew = fmaxf(mold, mt);
            m_s[tid] = mnew;
            sc_s[tid] = __expf(mold - mnew);
        }
        __syncthreads();
        // exp + write P (fp16) into the dead K[buf] stage buffer
        __half* Ph = (__half*)(smc + OFFB_K + buf * KV_TILE_BYTES);
        {
            float mnew = m_s[srow];
            float e16[16];
            float sum = 0.0f;
#pragma unroll
            for (int j = 0; j < 16; ++j) {
                e16[j] = __expf(Ss[srow * FS_ST + sq * 16 + j] - mnew);
                sum += e16[j];
            }
#pragma unroll
            for (int j = 0; j < 16; j += 2)
                *(__half2*)(Ph + srow * FP_STH + sq * 16 + j) =
                    __floats2half2_rn(e16[j], e16[j + 1]);
            red[sq * 64 + srow] = sum;
        }
        __syncthreads();
        if (tid < BQ) {
            l_s[tid] = l_s[tid] * sc_s[tid] +
                       (red[tid] + red[64 + tid] + red[128 + tid] + red[192 + tid]);
        }

        // ---- rescale O, then O += P @ V (16x64 warp tile, K=64, ks=4) ----
        const float scr0 = sc_s[r0];
        const float scr1 = sc_s[r0 + 8];
#pragma unroll
        for (int nf = 0; nf < 8; ++nf) {
            accO[nf][0] *= scr0;
            accO[nf][1] *= scr0;
            accO[nf][2] *= scr1;
            accO[nf][3] *= scr1;
        }

        const uint32_t* Pw = (const uint32_t*)Ph + (warp_m * 16 + lr) * FP_STW + kc;
        const uint32_t vbase = v_su + buf * KV_TILE_BYTES + (warp_n * 64) * 2;
#pragma unroll
        for (int ks = 0; ks < 4; ++ks) {
            uint32_t a[4];
            const uint32_t* ap = Pw + ks * 8;
            a[0] = ap[0];
            a[1] = ap[8 * FP_STW];
            a[2] = ap[4];
            a[3] = ap[8 * FP_STW + 4];
            const uint32_t rowaddr = vbase + ((ks * 16 + (lane & 15)) * FSTH) * 2;
#pragma unroll
            for (int nf = 0; nf < 8; ++nf) {
                uint32_t bfr[2];
                ldmatrix_x2_trans(bfr[0], bfr[1], rowaddr + nf * 16);
                mma_f16(accO[nf], a, bfr);
            }
        }
        __syncthreads();   // P + V reads done before next prefetch overwrites
    }

    // ---- normalize + write O fp16 ----
    const int row0 = warp_m * 16 + lr;
    const float inv0 = 1.0f / l_s[row0];
    const float inv1 = 1.0f / l_s[row0 + 8];
    __half* Og = O + head_base + (size_t)(qt * BQ) * DIM;
#pragma unroll
    for (int nf = 0; nf < 8; ++nf) {
        int col = warp_n * 64 + nf * 8 + kc * 2;
        *(__half2*)(Og + (size_t)row0 * DIM + col) =
            __floats2half2_rn(accO[nf][0] * inv0, accO[nf][1] * inv0);
        *(__half2*)(Og + (size_t)(row0 + 8) * DIM + col) =
            __floats2half2_rn(accO[nf][2] * inv1, accO[nf][3] * inv1);
    }
}

// ---------------------------------------------------------------------------
// Launch. Inputs: 0=x, 1=start_pos, 2=freqs_cos, 3=freqs_sin, 4=mask,
// 5=wq, 6=wk, 7=wv, 8=wo. Output: (B, S, DIM) fp32.
// ---------------------------------------------------------------------------
extern "C" void kernel_launch(void* const* d_in, const int* in_sizes, int n_in,
                              void* d_out, int out_size)
{
    const float* x  = (const float*)d_in[0];
    const float* fc = (const float*)d_in[2];
    const float* fs = (const float*)d_in[3];
    const float* wq = (const float*)d_in[5];
    const float* wk = (const float*)d_in[6];
    const float* wv = (const float*)d_in[7];
    const float* wo = (const float*)d_in[8];
    float* out = (float*)d_out;

    __half *qp, *kp, *vp, *ap, *xh, *wqh, *wkh, *wvh, *woh;
    cudaGetSymbolAddress((void**)&qp, g_q);
    cudaGetSymbolAddress((void**)&kp, g_k);
    cudaGetSymbolAddress((void**)&vp, g_v);
    cudaGetSymbolAddress((void**)&ap, g_att);
    cudaGetSymbolAddress((void**)&xh, g_xh);
    cudaGetSymbolAddress((void**)&wqh, g_wqh);
    cudaGetSymbolAddress((void**)&wkh, g_wkh);
    cudaGetSymbolAddress((void**)&wvh, g_wvh);
    cudaGetSymbolAddress((void**)&woh, g_woh);

    // pre-convert inputs to fp16
    const int n4x = (MROWS * DIM) / 4;
    const int n4w = (DIM * DIM) / 4;
    cvt_f16_kernel<<<(n4x + 255) / 256, 256>>>((const float4*)x, (uint2*)xh, n4x);
    cvt_f16_kernel<<<(n4w + 255) / 256, 256>>>((const float4*)wq, (uint2*)wqh, n4w);
    cvt_f16_kernel<<<(n4w + 255) / 256, 256>>>((const float4*)wk, (uint2*)wkh, n4w);
    cvt_f16_kernel<<<(n4w + 255) / 256, 256>>>((const float4*)wv, (uint2*)wvh, n4w);
    cvt_f16_kernel<<<(n4w + 255) / 256, 256>>>((const float4*)wo, (uint2*)woh, n4w);

    cudaFuncSetAttribute(gemm_f16_kernel,
                         cudaFuncAttributeMaxDynamicSharedMemorySize, GEMM_SMEM);

    // fused QKV projection + RoPE (+1/sqrt(hd) folded into q) -> fp16
    dim3 gq(DIM / GBN, MROWS / GBM, 3);
    gemm_f16_kernel<<<gq, 256, GEMM_SMEM>>>(xh, wqh, wkh, wvh,
                                            qp, kp, vp, fc, fs, 1);

    // flash attention (fp16 in/out)
    cudaFuncSetAttribute(flash_kernel,
                         cudaFuncAttributeMaxDynamicSharedMemorySize,
                         FLASH_SMEM_BYTES);
    dim3 fg(SEQLEN / BQ, BSZ * NH);
    flash_kernel<<<fg, 256, FLASH_SMEM_BYTES>>>(qp, kp, vp, ap);

    // output projection -> fp32
    dim3 go(DIM / GBN, MROWS / GBM, 1);
    gemm_f16_kernel<<<go, 256, GEMM_SMEM>>>(ap, woh, woh, woh,
                                            out, out, out, fc, fs, 0);
}

// round 15
// speedup vs baseline: 1.1761x; 1.1761x over previous
#include <cuda_runtime.h>
#include <cuda_fp16.h>
#include <cstdint>
#include <math.h>

#define DIM 2048
#define NH 16
#define HD 128
#define BSZ 2
#define SEQLEN 2048
#define MROWS (BSZ * SEQLEN)

// Scratch (static device arrays — allocation-free per harness rules)
__device__ __half g_q[(size_t)MROWS * DIM];
__device__ __half g_k[(size_t)MROWS * DIM];
__device__ __half g_v[(size_t)MROWS * DIM];
__device__ __half g_att[(size_t)MROWS * DIM];
__device__ __half g_xh[(size_t)MROWS * DIM];
__device__ __half g_wqh[(size_t)DIM * DIM];
__device__ __half g_wkh[(size_t)DIM * DIM];
__device__ __half g_wvh[(size_t)DIM * DIM];
__device__ __half g_woh[(size_t)DIM * DIM];

__device__ __forceinline__ void mma_f16(float* c, const uint32_t* a,
                                        const uint32_t* b) {
    asm volatile(
        "mma.sync.aligned.m16n8k16.row.col.f32.f16.f16.f32 "
        "{%0,%1,%2,%3}, {%4,%5,%6,%7}, {%8,%9}, {%0,%1,%2,%3};"
        : "+f"(c[0]), "+f"(c[1]), "+f"(c[2]), "+f"(c[3])
        : "r"(a[0]), "r"(a[1]), "r"(a[2]), "r"(a[3]), "r"(b[0]), "r"(b[1]));
}

__device__ __forceinline__ void ldmatrix_x2_trans(uint32_t& r0, uint32_t& r1,
                                                  uint32_t addr) {
    asm volatile("ldmatrix.sync.aligned.m8n8.x2.trans.shared.b16 {%0,%1}, [%2];"
                 : "=r"(r0), "=r"(r1) : "r"(addr));
}

__device__ __forceinline__ uint32_t smem_u32(const void* p) {
    uint32_t a;
    asm("{ .reg .u64 t; cvta.to.shared.u64 t, %1; cvt.u32.u64 %0, t; }"
        : "=r"(a) : "l"(p));
    return a;
}
__device__ __forceinline__ void cp_async16(uint32_t dst, const void* src) {
    asm volatile("cp.async.cg.shared.global [%0], [%1], 16;"
                 :: "r"(dst), "l"(src) : "memory");
}
#define CP_COMMIT() asm volatile("cp.async.commit_group;" ::: "memory")
#define CP_WAIT(N)  asm volatile("cp.async.wait_group %0;" :: "n"(N) : "memory")

// ---------------------------------------------------------------------------
// fp32 -> fp16 elementwise convert (vectorized)
// ---------------------------------------------------------------------------
__global__ __launch_bounds__(256) void cvt_f16_kernel(
    const float4* __restrict__ in, uint2* __restrict__ out, int n4)
{
    int i = blockIdx.x * blockDim.x + threadIdx.x;
    if (i >= n4) return;
    float4 v = in[i];
    __half2 h0 = __floats2half2_rn(v.x, v.y);
    __half2 h1 = __floats2half2_rn(v.z, v.w);
    uint2 u;
    u.x = *(uint32_t*)&h0;
    u.y = *(uint32_t*)&h1;
    out[i] = u;
}

// ===========================================================================
// fp16 mma.sync GEMM (R10-proven config): C = A * B^T. A [M][K], B [N][K].
// 128x128x32 block tile, 8 warps (2x4), warp tile 64x32, m16n8k16,
// 3-buffer cp.async pipeline, 2 CTAs/SM.
// qkv_mode: outputs fp16 with RoPE (z<2) and q-scale (z==0); else fp32 out.
// ===========================================================================
#define GBM 128
#define GBN 128
#define GBK 32
#define GSTH 40                 // halfs per smem row (20 words: conflict-free)
#define GSTW 20
#define GT_H (GBM * GSTH)       // 5120 halfs
#define GT_W (GT_H / 2)         // 2560 words
#define GSTAGE_H (2 * GT_H)
#define GNBUF 3
#define GEMM_SMEM (GNBUF * GSTAGE_H * 2)   // 61440 bytes
#define NSTAGE (DIM / GBK)                 // 64

__global__ __launch_bounds__(256, 2) void gemm_f16_kernel(
    const __half* __restrict__ A,
    const __half* __restrict__ B0, const __half* __restrict__ B1,
    const __half* __restrict__ B2,
    void* C0, void* C1, void* C2,
    const float* __restrict__ cosf, const float* __restrict__ sinf,
    int qkv_mode)
{
    extern __shared__ __half smh[];
    const int tid = threadIdx.x;
    const int wid = tid >> 5;
    const int lane = tid & 31;
    const int warp_m = wid >> 2;
    const int warp_n = wid & 3;
    const int bm = blockIdx.y * GBM;
    const int bn = blockIdx.x * GBN;
    const int z = blockIdx.z;

    const __half* B = (z == 0) ? B0 : (z == 1) ? B1 : B2;
    void* C = (z == 0) ? C0 : (z == 1) ? C1 : C2;

    const uint32_t smem_base = smem_u32(smh);

    float acc[4][4][4];
#pragma unroll
    for (int i = 0; i < 4; ++i)
#pragma unroll
        for (int j = 0; j < 4; ++j)
#pragma unroll
            for (int r = 0; r < 4; ++r) acc[i][j][r] = 0.0f;

    // per-stage: A,B tiles 128 rows x 32 halfs; 4 x 16B chunks per row
    const int pr4 = tid >> 2;      // 0..63
    const int pc4 = tid & 3;       // 0..3
    auto prefetch = [&](int s) {
        const int k0 = s * GBK;
        const uint32_t sb = smem_base + (s % GNBUF) * (GSTAGE_H * 2);
#pragma unroll
        for (int i = 0; i < 2; ++i) {
            int r = pr4 + i * 64;
            cp_async16(sb + (r * GSTH + pc4 * 8) * 2,
                       A + (size_t)(bm + r) * DIM + k0 + pc4 * 8);
            cp_async16(sb + (GT_H + r * GSTH + pc4 * 8) * 2,
                       B + (size_t)(bn + r) * DIM + k0 + pc4 * 8);
        }
        CP_COMMIT();
    };

    prefetch(0);
    prefetch(1);

    const int arow = warp_m * 64 + (lane >> 2);
    const int brow = warp_n * 32 + (lane >> 2);
    const int kc = lane & 3;

    for (int s = 0; s < NSTAGE; ++s) {
        if (s + 1 < NSTAGE) { CP_WAIT(1); } else { CP_WAIT(0); }
        __syncthreads();
        if (s + 2 < NSTAGE) prefetch(s + 2);   // after sync: WAR-safe

        const uint32_t* Asm = (const uint32_t*)smh + (s % GNBUF) * (GSTAGE_H / 2);
        const uint32_t* Bsm = Asm + GT_W;

#pragma unroll
        for (int ks = 0; ks < 2; ++ks) {
            uint32_t af[4][4];
#pragma unroll
            for (int mt = 0; mt < 4; ++mt) {
                const uint32_t* p = Asm + (arow + mt * 16) * GSTW + ks * 8 + kc;
                af[mt][0] = p[0];
                af[mt][1] = p[8 * GSTW];
                af[mt][2] = p[4];
                af[mt][3] = p[8 * GSTW + 4];
            }
            uint32_t bf[4][2];
#pragma unroll
            for (int nt = 0; nt < 4; ++nt) {
                const uint32_t* p = Bsm + (brow + nt * 8) * GSTW + ks * 8 + kc;
                bf[nt][0] = p[0];
                bf[nt][1] = p[4];
            }
#pragma unroll
            for (int mt = 0; mt < 4; ++mt)
#pragma unroll
                for (int nt = 0; nt < 4; ++nt)
                    mma_f16(acc[mt][nt], af[mt], bf[nt]);
        }
    }

    // epilogue
    const float qs = (qkv_mode && z == 0) ? 0.08838834764831845f : 1.0f;
#pragma unroll
    for (int mt = 0; mt < 4; ++mt) {
        const int row0 = bm + warp_m * 64 + mt * 16 + (lane >> 2);
        const int s0 = row0 & (SEQLEN - 1);
#pragma unroll
        for (int nt = 0; nt < 4; ++nt) {
            const int col = bn + warp_n * 32 + nt * 8 + (lane & 3) * 2;
            float v0 = acc[mt][nt][0], v1 = acc[mt][nt][1];
            float v2 = acc[mt][nt][2], v3 = acc[mt][nt][3];
            if (qkv_mode) {
                if (z < 2) {   // RoPE for q, k
                    const int p = (col & (HD - 1)) >> 1;
                    float c0 = cosf[s0 * 64 + p], n0 = sinf[s0 * 64 + p];
                    float c1 = cosf[(s0 + 8) * 64 + p], n1 = sinf[(s0 + 8) * 64 + p];
                    float t0 = v0 * c0 - v1 * n0;
                    v1 = v0 * n0 + v1 * c0; v0 = t0;
                    float t2 = v2 * c1 - v3 * n1;
                    v3 = v2 * n1 + v3 * c1; v2 = t2;
                }
                __half* Ch = (__half*)C;
                *(__half2*)(Ch + (size_t)row0 * DIM + col) =
                    __floats2half2_rn(v0 * qs, v1 * qs);
                *(__half2*)(Ch + (size_t)(row0 + 8) * DIM + col) =
                    __floats2half2_rn(v2 * qs, v3 * qs);
            } else {
                float* Cf = (float*)C;
                *(float2*)(Cf + (size_t)row0 * DIM + col) = make_float2(v0, v1);
                *(float2*)(Cf + (size_t)(row0 + 8) * DIM + col) = make_float2(v2, v3);
            }
        }
    }
}

// ===========================================================================
// Flash attention, fp16 mma.sync. BQ=64, BKV=64, 256 threads, 2 CTAs/SM.
// Q pre-scaled by 1/sqrt(hd). QK^T warp tile 16x32; PV 16x64 (V via
// ldmatrix.trans). P (fp16) is aliased into the DEAD K[buf] stage buffer:
// K[buf] reads end before the post-scores sync; next prefetch into K[buf]
// happens after the loop-end sync, so the overlay is race-free.
// ===========================================================================
#define BQ 64
#define BKV 64
#define FSTH 136          // Q/K/V smem stride in halfs (68 words)
#define FSTW 68
#define FS_ST 68          // S stride (floats)
#define FP_STH 72         // P stride (halfs) = 36 words: conflict-free A-frags
#define FP_STW 36

#define Q_BYTES (BQ * FSTH * 2)           // 17408
#define KV_TILE_BYTES (BKV * FSTH * 2)    // 17408
#define OFFB_Q 0
#define OFFB_K (OFFB_Q + Q_BYTES)                 // 17408
#define OFFB_V (OFFB_K + 2 * KV_TILE_BYTES)       // 52224
#define OFFB_S (OFFB_V + 2 * KV_TILE_BYTES)       // 87040
#define OFFB_RED (OFFB_S + BQ * FS_ST * 4)        // 104448
#define OFFB_M (OFFB_RED + 256 * 4)               // 105472
#define OFFB_L (OFFB_M + BQ * 4)
#define OFFB_SC (OFFB_L + BQ * 4)
#define FLASH_SMEM_BYTES (OFFB_SC + BQ * 4)       // 106240

__global__ __launch_bounds__(256, 2) void flash_kernel(
    const __half* __restrict__ Q, const __half* __restrict__ K,
    const __half* __restrict__ V, __half* __restrict__ O)
{
    extern __shared__ char smc[];
    __half* Qs = (__half*)(smc + OFFB_Q);
    float* Ss = (float*)(smc + OFFB_S);
    float* red = (float*)(smc + OFFB_RED);
    float* m_s = (float*)(smc + OFFB_M);
    float* l_s = (float*)(smc + OFFB_L);
    float* sc_s = (float*)(smc + OFFB_SC);

    const int qt = (int)gridDim.x - 1 - (int)blockIdx.x;   // heavy tiles first
    const int bh = blockIdx.y;
    const int b = bh >> 4;
    const int h = bh & 15;
    const int tid = threadIdx.x;
    const int wid = tid >> 5;
    const int lane = tid & 31;
    const int warp_m = wid >> 1;     // 0..3
    const int warp_n = wid & 1;      // 0..1
    const int lr = lane >> 2;        // 0..7
    const int kc = lane & 3;         // 0..3

    const size_t head_base = (size_t)b * SEQLEN * DIM + (size_t)h * HD;
    const uint32_t q_su = smem_u32(smc + OFFB_Q);
    const uint32_t k_su = smem_u32(smc + OFFB_K);
    const uint32_t v_su = smem_u32(smc + OFFB_V);

    // Load Q tile via cp.async (fp16, already scaled)
    {
        const __half* Qg = Q + head_base + (size_t)(qt * BQ) * DIM;
#pragma unroll
        for (int i = 0; i < 4; ++i) {
            int e = tid + i * 256;        // 0..1023
            int r = e >> 4;               // 0..63
            int c = e & 15;               // 16B chunk (8 halfs)
            cp_async16(q_su + (r * FSTH + c * 8) * 2,
                       Qg + (size_t)r * DIM + c * 8);
        }
        CP_COMMIT();
    }
    if (tid < BQ) { m_s[tid] = -1e30f; l_s[tid] = 0.0f; }

    float accO[8][4];
#pragma unroll
    for (int i = 0; i < 8; ++i)
#pragma unroll
        for (int r = 0; r < 4; ++r) accO[i][r] = 0.0f;

    auto prefetch = [&](int kt, int buf) {
        const __half* Kg = K + head_base + (size_t)(kt * BKV) * DIM;
        const __half* Vg = V + head_base + (size_t)(kt * BKV) * DIM;
        const uint32_t kb = k_su + buf * KV_TILE_BYTES;
        const uint32_t vb = v_su + buf * KV_TILE_BYTES;
#pragma unroll
        for (int i = 0; i < 4; ++i) {
            int e = tid + i * 256;        // 0..1023
            int r = e >> 4;               // 0..63
            int c = e & 15;
            cp_async16(kb + (r * FSTH + c * 8) * 2, Kg + (size_t)r * DIM + c * 8);
            cp_async16(vb + (r * FSTH + c * 8) * 2, Vg + (size_t)r * DIM + c * 8);
        }
        CP_COMMIT();
    };

    prefetch(0, 0);
    __syncthreads();

    const int ntiles = qt + 1;
    for (int kt = 0; kt < ntiles; ++kt) {
        const int buf = kt & 1;
        const bool more = (kt + 1 < ntiles);
        if (more) prefetch(kt + 1, buf ^ 1);
        if (more) { CP_WAIT(1); } else { CP_WAIT(0); }
        __syncthreads();

        // ---- QK^T: 16x32 warp tile, m16n8k16, ks = HD/16 = 8 ----
        float accS[4][4];
#pragma unroll
        for (int nt = 0; nt < 4; ++nt)
#pragma unroll
            for (int r = 0; r < 4; ++r) accS[nt][r] = 0.0f;

        const uint32_t* Qw = (const uint32_t*)Qs + (warp_m * 16 + lr) * FSTW + kc;
        const uint32_t* Kw = (const uint32_t*)(smc + OFFB_K) +
                             buf * (KV_TILE_BYTES / 4) +
                             (warp_n * 32 + lr) * FSTW + kc;
#pragma unroll
        for (int ks = 0; ks < 8; ++ks) {
            uint32_t a[4];
            const uint32_t* ap = Qw + ks * 8;
            a[0] = ap[0];
            a[1] = ap[8 * FSTW];
            a[2] = ap[4];
            a[3] = ap[8 * FSTW + 4];
#pragma unroll
            for (int nt = 0; nt < 4; ++nt) {
                const uint32_t* bp = Kw + nt * 8 * FSTW + ks * 8;
                uint32_t bfr[2];
                bfr[0] = bp[0];
                bfr[1] = bp[4];
                mma_f16(accS[nt], a, bfr);
            }
        }

        // ---- store scores fp32 (causal mask on diagonal tile kt==qt) ----
        const bool diag = (kt == qt);
        const int r0 = warp_m * 16 + lr;
#pragma unroll
        for (int nt = 0; nt < 4; ++nt) {
            int cb = warp_n * 32 + nt * 8 + kc * 2;
            float v0 = accS[nt][0], v1 = accS[nt][1];
            float v2 = accS[nt][2], v3 = accS[nt][3];
            if (diag) {
                if (cb > r0)          v0 = -1e30f;
                if (cb + 1 > r0)      v1 = -1e30f;
                if (cb > r0 + 8)      v2 = -1e30f;
                if (cb + 1 > r0 + 8)  v3 = -1e30f;
            }
            Ss[r0 * FS_ST + cb]           = v0;
            Ss[r0 * FS_ST + cb + 1]       = v1;
            Ss[(r0 + 8) * FS_ST + cb]     = v2;
            Ss[(r0 + 8) * FS_ST + cb + 1] = v3;
        }
        __syncthreads();   // also: all K[buf] reads complete (P overlay safe)

        // ---- softmax: 4 threads per row, 16 cols each ----
        const int srow = tid & 63;
        const int sq = tid >> 6;
        {
            float mx = -1e30f;
#pragma unroll
            for (int j = 0; j < 16; ++j)
                mx = fmaxf(mx, Ss[srow * FS_ST + sq * 16 + j]);
            red[sq * 64 + srow] = mx;
        }
        __syncthreads();
        if (tid < BQ) {
            float mold = m_s[tid];
            float mt = fmaxf(fmaxf(red[tid], red[64 + tid]),
                             fmaxf(red[128 + tid], red[192 + tid]));
            float mnew = fmaxf(mold, mt);
            m_s[tid] = mnew;
            sc_s[tid] = __expf(mold - mnew);
        }
        __syncthreads();
        // exp + write P (fp16) into the dead K[buf] stage buffer
        __half* Ph = (__half*)(smc + OFFB_K + buf * KV_TILE_BYTES);
        {
            float mnew = m_s[srow];
            float e16[16];
            float sum = 0.0f;
#pragma unroll
            for (int j = 0; j < 16; ++j) {
                e16[j] = __expf(Ss[srow * FS_ST + sq * 16 + j] - mnew);
                sum += e16[j];
            }
#pragma unroll
            for (int j = 0; j < 16; j += 2)
                *(__half2*)(Ph + srow * FP_STH + sq * 16 + j) =
                    __floats2half2_rn(e16[j], e16[j + 1]);
            red[sq * 64 + srow] = sum;
        }
        __syncthreads();
        if (tid < BQ) {
            l_s[tid] = l_s[tid] * sc_s[tid] +
                       (red[tid] + red[64 + tid] + red[128 + tid] + red[192 + tid]);
        }

        // ---- rescale O, then O += P @ V (16x64 warp tile, K=64, ks=4) ----
        const float scr0 = sc_s[r0];
        const float scr1 = sc_s[r0 + 8];
#pragma unroll
        for (int nf = 0; nf < 8; ++nf) {
            accO[nf][0] *= scr0;
            accO[nf][1] *= scr0;
            accO[nf][2] *= scr1;
            accO[nf][3] *= scr1;
        }

        const uint32_t* Pw = (const uint32_t*)Ph + (warp_m * 16 + lr) * FP_STW + kc;
        const uint32_t vbase = v_su + buf * KV_TILE_BYTES + (warp_n * 64) * 2;
#pragma unroll
        for (int ks = 0; ks < 4; ++ks) {
            uint32_t a[4];
            const uint32_t* ap = Pw + ks * 8;
            a[0] = ap[0];
            a[1] = ap[8 * FP_STW];
            a[2] = ap[4];
            a[3] = ap[8 * FP_STW + 4];
            const uint32_t rowaddr = vbase + ((ks * 16 + (lane & 15)) * FSTH) * 2;
#pragma unroll
            for (int nf = 0; nf < 8; ++nf) {
                uint32_t bfr[2];
                ldmatrix_x2_trans(bfr[0], bfr[1], rowaddr + nf * 16);
                mma_f16(accO[nf], a, bfr);
            }
        }
        __syncthreads();   // P + V reads done before next prefetch overwrites
    }

    // ---- normalize + write O fp16 ----
    const int row0 = warp_m * 16 + lr;
    const float inv0 = 1.0f / l_s[row0];
    const float inv1 = 1.0f / l_s[row0 + 8];
    __half* Og = O + head_base + (size_t)(qt * BQ) * DIM;
#pragma unroll
    for (int nf = 0; nf < 8; ++nf) {
        int col = warp_n * 64 + nf * 8 + kc * 2;
        *(__half2*)(Og + (size_t)row0 * DIM + col) =
            __floats2half2_rn(accO[nf][0] * inv0, accO[nf][1] * inv0);
        *(__half2*)(Og + (size_t)(row0 + 8) * DIM + col) =
            __floats2half2_rn(accO[nf][2] * inv1, accO[nf][3] * inv1);
    }
}

// ---------------------------------------------------------------------------
// Launch. Inputs: 0=x, 1=start_pos, 2=freqs_cos, 3=freqs_sin, 4=mask,
// 5=wq, 6=wk, 7=wv, 8=wo. Output: (B, S, DIM) fp32.
// ---------------------------------------------------------------------------
extern "C" void kernel_launch(void* const* d_in, const int* in_sizes, int n_in,
                              void* d_out, int out_size)
{
    const float* x  = (const float*)d_in[0];
    const float* fc = (const float*)d_in[2];
    const float* fs = (const float*)d_in[3];
    const float* wq = (const float*)d_in[5];
    const float* wk = (const float*)d_in[6];
    const float* wv = (const float*)d_in[7];
    const float* wo = (const float*)d_in[8];
    float* out = (float*)d_out;

    __half *qp, *kp, *vp, *ap, *xh, *wqh, *wkh, *wvh, *woh;
    cudaGetSymbolAddress((void**)&qp, g_q);
    cudaGetSymbolAddress((void**)&kp, g_k);
    cudaGetSymbolAddress((void**)&vp, g_v);
    cudaGetSymbolAddress((void**)&ap, g_att);
    cudaGetSymbolAddress((void**)&xh, g_xh);
    cudaGetSymbolAddress((void**)&wqh, g_wqh);
    cudaGetSymbolAddress((void**)&wkh, g_wkh);
    cudaGetSymbolAddress((void**)&wvh, g_wvh);
    cudaGetSymbolAddress((void**)&woh, g_woh);

    // pre-convert inputs to fp16
    const int n4x = (MROWS * DIM) / 4;
    const int n4w = (DIM * DIM) / 4;
    cvt_f16_kernel<<<(n4x + 255) / 256, 256>>>((const float4*)x, (uint2*)xh, n4x);
    cvt_f16_kernel<<<(n4w + 255) / 256, 256>>>((const float4*)wq, (uint2*)wqh, n4w);
    cvt_f16_kernel<<<(n4w + 255) / 256, 256>>>((const float4*)wk, (uint2*)wkh, n4w);
    cvt_f16_kernel<<<(n4w + 255) / 256, 256>>>((const float4*)wv, (uint2*)wvh, n4w);
    cvt_f16_kernel<<<(n4w + 255) / 256, 256>>>((const float4*)wo, (uint2*)woh, n4w);

    cudaFuncSetAttribute(gemm_f16_kernel,
                         cudaFuncAttributeMaxDynamicSharedMemorySize, GEMM_SMEM);

    // fused QKV projection + RoPE (+1/sqrt(hd) folded into q) -> fp16
    dim3 gq(DIM / GBN, MROWS / GBM, 3);
    gemm_f16_kernel<<<gq, 256, GEMM_SMEM>>>(xh, wqh, wkh, wvh,
                                            qp, kp, vp, fc, fs, 1);

    // flash attention (fp16 in/out)
    cudaFuncSetAttribute(flash_kernel,
                         cudaFuncAttributeMaxDynamicSharedMemorySize,
                         FLASH_SMEM_BYTES);
    dim3 fg(SEQLEN / BQ, BSZ * NH);
    flash_kernel<<<fg, 256, FLASH_SMEM_BYTES>>>(qp, kp, vp, ap);

    // output projection -> fp32
    dim3 go(DIM / GBN, MROWS / GBM, 1);
    gemm_f16_kernel<<<go, 256, GEMM_SMEM>>>(ap, woh, woh, woh,
                                            out, out, out, fc, fs, 0);
}